// round 10
// baseline (speedup 1.0000x reference)
#include <cuda_runtime.h>

#define V_NODES 2048
#define D_F     128
#define NBLK    128            // scatter blocks
#define NPB     16             // nodes per scatter block
#define NK      73             // 1 + 8 + 64 output coefficient rows
#define NOUT    (NK * D_F)     // 9344
#define CHUNKS  512            // row chunks for degree partial sums
#define ROWS_PER 4             // rows per chunk (CHUNKS * ROWS_PER = V_NODES)
#define RED_IBLK 37            // ceil(NOUT/256) -- out zeroing blocks

// Scratch (static device globals — no allocation allowed)
__device__ float g_degp[CHUNKS * V_NODES];     // per-chunk column partial sums (4 MB)
__device__ float g_partial[NBLK * NK * D_F];   // block-major scattering partials
__device__ int   g_ct;                         // barrier counter (monotonic across replays)

// ---------------------------------------------------------------------------
// Kernel 1: column partial sums of W (symmetric => column sum == row sum).
// 1024 blocks x 256 threads (-> ~55 warps/SM residency). Each thread: 4
// independent float4 loads, tree sum, one float4 store. Blocks 0..36 also
// zero the output buffer (kernel boundary orders this before the atomics).
// ---------------------------------------------------------------------------
__global__ void __launch_bounds__(256) deg_part_kernel(const float* __restrict__ W,
                                                       float* __restrict__ out) {
    const int g  = blockIdx.x & 1;
    const int rc = blockIdx.x >> 1;
    const int c4 = g * 256 + threadIdx.x;          // float4 column index [0,512)

    if (blockIdx.x < RED_IBLK) {
        int i = blockIdx.x * 256 + threadIdx.x;
        if (i < NOUT) out[i] = 0.f;
    }

    const float4* base = (const float4*)W + (size_t)rc * ROWS_PER * 512 + c4;

    float4 v0 = base[0 * 512];
    float4 v1 = base[1 * 512];
    float4 v2 = base[2 * 512];
    float4 v3 = base[3 * 512];

    float4 a;
    a.x = (v0.x + v1.x) + (v2.x + v3.x);
    a.y = (v0.y + v1.y) + (v2.y + v3.y);
    a.z = (v0.z + v1.z) + (v2.z + v3.z);
    a.w = (v0.w + v1.w) + (v2.w + v3.w);

    ((float4*)(g_degp + (size_t)rc * V_NODES))[c4] = a;
}

// ---------------------------------------------------------------------------
// Kernel 2: scattering + in-kernel reduce.
// 128 blocks x 256 threads — exactly one wave (1 block/SM), so the epoch
// grid barrier is deadlock-free and cheap. Phase A computes per-block
// partials (as before); barrier; phase B: 2 threads per output each sum 64
// block-partials (L2-hot) and atomicAdd into out (2 adds per address).
// ---------------------------------------------------------------------------
__global__ void __launch_bounds__(256) scat_kernel(const float* __restrict__ f,
                                                   float* __restrict__ out) {
    __shared__ float lam_s[8][NPB];
    __shared__ float deg_sh[NPB];
    __shared__ float comb[NK][D_F];
    __shared__ int   s_target;

    const int b = blockIdx.x;
    const int tid = threadIdx.x;
    const int half = tid >> 7;       // 0 or 1
    const int d = tid & 127;         // feature index

    // --- finalize degrees: 512 chunk partials per node, 16 lanes per node ---
    {
        const int n = tid >> 4;      // node within tile [0,16)
        const int sub = tid & 15;
        float s = 0.f;
#pragma unroll
        for (int k = 0; k < 32; k++)
            s += g_degp[(size_t)(sub + 16 * k) * V_NODES + b * NPB + n];
#pragma unroll
        for (int off = 8; off; off >>= 1)
            s += __shfl_down_sync(0xffffffffu, s, off, 16);
        if (sub == 0) deg_sh[n] = s;
    }
    __syncthreads();

    if (tid < NPB) {
        float dg = deg_sh[tid];
        float inv = 1.0f / fmaxf(1.0f, dg);       // dhalf^2 with clamp
        float E = fabsf(dg * inv);                // |eigenvalue| for this node
        float logE = logf(E);
        const float Ac = 0.34657359027997264f;    // A = 3*ln(2)/6
        float s = 1.125f;                         // (R/2)*sum(d^2) + (R/2)*d0^2
#pragma unroll
        for (int j = 2; j <= 8; j++) {
            float x = logE - Ac * (float)(j - 1) * (1.0f / 3.0f);
            float w = 0.0f;
            if (x > -Ac && x <= 0.0f)
                w = 0.5f - 0.5f * cosf(x * (6.283185307179586f / Ac));
            lam_s[j - 1][tid] = w;
            s -= w * w;
        }
        lam_s[0][tid] = sqrtf(fmaxf(s, 0.0f));    // scaling function
    }
    __syncthreads();

    // Each half handles 8 nodes x 1 feature per thread.
    const int n0 = half * 8;
    float fv[8];
#pragma unroll
    for (int n = 0; n < 8; n++)
        fv[n] = f[(size_t)(b * NPB + n0 + n) * D_F + d];

    float acc[NK];
#pragma unroll
    for (int k = 0; k < NK; k++) acc[k] = 0.f;

#pragma unroll
    for (int n = 0; n < 8; n++) {
        float v = fv[n];
        float af = fabsf(v);
        acc[0] += v;
        float l[8];
#pragma unroll
        for (int j = 0; j < 8; j++) l[j] = lam_s[j][n0 + n];   // smem broadcast
#pragma unroll
        for (int j = 0; j < 8; j++) acc[1 + j] += l[j] * af;
#pragma unroll
        for (int j1 = 0; j1 < 8; j1++) {
            float t = l[j1] * af;
#pragma unroll
            for (int j2 = 0; j2 < 8; j2++)
                acc[9 + j1 * 8 + j2] += l[j2] * t;
        }
    }

    // Combine halves through smem, half 1 stores this block's partials.
    if (half == 0) {
#pragma unroll
        for (int k = 0; k < NK; k++) comb[k][d] = acc[k];
    }
    __syncthreads();
    if (half == 1) {
        float* p = g_partial + (size_t)b * NOUT + d;
#pragma unroll
        for (int k = 0; k < NK; k++)
            p[k * D_F] = acc[k] + comb[k][d];
    }

    // ---------------- Grid barrier (128 co-resident blocks) ----------------
    __threadfence();                 // publish g_partial before arriving
    __syncthreads();
    if (tid == 0) {
        int old = atomicAdd(&g_ct, 1);
        s_target = (old / NBLK + 1) * NBLK;
    }
    __syncthreads();
    if (tid == 0) {
        while (*(volatile int*)&g_ct < s_target)
            __nanosleep(32);
    }
    __syncthreads();
    __threadfence();                 // acquire: see all blocks' partials

    // ---------------- Phase B: parallel reduce ----------------
    // 2 threads per output; each sums 64 of the 128 block-partials.
    const int gtid = b * 256 + tid;
    if (gtid < 2 * NOUT) {
        const int i = gtid >> 1;
        const int part = gtid & 1;
        const float* p = g_partial + (size_t)part * 64 * NOUT + i;
        float s0 = 0.f, s1 = 0.f, s2 = 0.f, s3 = 0.f;
        float s4 = 0.f, s5 = 0.f, s6 = 0.f, s7 = 0.f;
#pragma unroll
        for (int k = 0; k < 64; k += 8) {
            s0 += p[(k + 0) * NOUT];
            s1 += p[(k + 1) * NOUT];
            s2 += p[(k + 2) * NOUT];
            s3 += p[(k + 3) * NOUT];
            s4 += p[(k + 4) * NOUT];
            s5 += p[(k + 5) * NOUT];
            s6 += p[(k + 6) * NOUT];
            s7 += p[(k + 7) * NOUT];
        }
        float s = (((s0 + s1) + (s2 + s3)) + ((s4 + s5) + (s6 + s7)));
        atomicAdd(out + i, s * (1.0f / (float)V_NODES));
    }
}

// ---------------------------------------------------------------------------
extern "C" void kernel_launch(void* const* d_in, const int* in_sizes, int n_in,
                              void* d_out, int out_size) {
    const float* W = (const float*)d_in[0];
    const float* f = (const float*)d_in[1];
    float* out = (float*)d_out;

    deg_part_kernel<<<2 * CHUNKS, 256>>>(W, out);
    scat_kernel<<<NBLK, 256>>>(f, out);
}

// round 12
// speedup vs baseline: 1.1880x; 1.1880x over previous
#include <cuda_runtime.h>

#define V_NODES 2048
#define D_F     128
#define NBLK    128            // scatter blocks
#define NPB     16             // nodes per scatter block
#define NK      73             // 1 + 8 + 64 output coefficient rows
#define NOUT    (NK * D_F)     // 9344
#define CHUNKS  512            // row chunks for degree partial sums
#define ROWS_PER 4             // rows per chunk (CHUNKS * ROWS_PER = V_NODES)
#define RED_IBLK 37            // ceil(NOUT/256) -- out zeroing blocks

// Scratch (static device globals — no allocation allowed)
__device__ float g_degp[CHUNKS * V_NODES];     // per-chunk column partial sums (4 MB)
__device__ float g_partial[NBLK * NK * D_F];   // block-major scattering partials
__device__ int   g_ct;                         // barrier counter (monotonic across replays)

// ---------------------------------------------------------------------------
// Kernel 1: column partial sums of W (symmetric => column sum == row sum).
// 1024 blocks x 256 threads. Each thread: 4 independent float4 loads, tree
// sum, one float4 store. Blocks 0..36 also zero the output buffer (the
// kernel boundary orders this before the fused kernel's atomics).
// ---------------------------------------------------------------------------
__global__ void __launch_bounds__(256) deg_part_kernel(const float* __restrict__ W,
                                                       float* __restrict__ out) {
    const int g  = blockIdx.x & 1;
    const int rc = blockIdx.x >> 1;
    const int c4 = g * 256 + threadIdx.x;          // float4 column index [0,512)

    if (blockIdx.x < RED_IBLK) {
        int i = blockIdx.x * 256 + threadIdx.x;
        if (i < NOUT) out[i] = 0.f;
    }

    const float4* base = (const float4*)W + (size_t)rc * ROWS_PER * 512 + c4;

    float4 v0 = base[0 * 512];
    float4 v1 = base[1 * 512];
    float4 v2 = base[2 * 512];
    float4 v3 = base[3 * 512];

    float4 a;
    a.x = (v0.x + v1.x) + (v2.x + v3.x);
    a.y = (v0.y + v1.y) + (v2.y + v3.y);
    a.z = (v0.z + v1.z) + (v2.z + v3.z);
    a.w = (v0.w + v1.w) + (v2.w + v3.w);

    ((float4*)(g_degp + (size_t)rc * V_NODES))[c4] = a;
}

// ---------------------------------------------------------------------------
// Kernel 2: scattering + in-kernel reduce.
// 128 blocks x 256 threads — exactly one wave, so the epoch grid barrier is
// deadlock-free. Degree prologue is COALESCED: thread (kk, c) sums 32
// chunk-partials; a warp covers two contiguous 64B segments per step. A 1KB
// smem transpose-reduce finishes the 16 node degrees.
// ---------------------------------------------------------------------------
__global__ void __launch_bounds__(256) scat_kernel(const float* __restrict__ f,
                                                   float* __restrict__ out) {
    __shared__ float lam_s[8][NPB];
    __shared__ float degp_sh[16][NPB];
    __shared__ float deg_sh[NPB];
    __shared__ float comb[NK][D_F];
    __shared__ int   s_target;

    const int b = blockIdx.x;
    const int tid = threadIdx.x;
    const int half = tid >> 7;       // 0 or 1
    const int d = tid & 127;         // feature index

    // --- coalesced degree finalize: 512 chunk partials per node ---
    {
        const int c  = tid & 15;     // node within tile
        const int kk = tid >> 4;     // chunk residue [0,16)
        const float* p = g_degp + (size_t)kk * V_NODES + b * NPB + c;
        float s = 0.f;
#pragma unroll
        for (int m = 0; m < 32; m++)
            s += p[(size_t)m * 16 * V_NODES];
        degp_sh[kk][c] = s;
    }
    __syncthreads();
    if (tid < NPB) {
        float s = 0.f;
#pragma unroll
        for (int k = 0; k < 16; k++)
            s += degp_sh[k][tid];
        deg_sh[tid] = s;
    }
    __syncthreads();

    if (tid < NPB) {
        float dg = deg_sh[tid];
        float inv = 1.0f / fmaxf(1.0f, dg);       // dhalf^2 with clamp
        float E = fabsf(dg * inv);                // |eigenvalue| for this node
        float logE = logf(E);
        const float Ac = 0.34657359027997264f;    // A = 3*ln(2)/6
        float s = 1.125f;                         // (R/2)*sum(d^2) + (R/2)*d0^2
#pragma unroll
        for (int j = 2; j <= 8; j++) {
            float x = logE - Ac * (float)(j - 1) * (1.0f / 3.0f);
            float w = 0.0f;
            if (x > -Ac && x <= 0.0f)
                w = 0.5f - 0.5f * cosf(x * (6.283185307179586f / Ac));
            lam_s[j - 1][tid] = w;
            s -= w * w;
        }
        lam_s[0][tid] = sqrtf(fmaxf(s, 0.0f));    // scaling function
    }
    __syncthreads();

    // Each half handles 8 nodes x 1 feature per thread.
    const int n0 = half * 8;
    float fv[8];
#pragma unroll
    for (int n = 0; n < 8; n++)
        fv[n] = f[(size_t)(b * NPB + n0 + n) * D_F + d];

    float acc[NK];
#pragma unroll
    for (int k = 0; k < NK; k++) acc[k] = 0.f;

#pragma unroll
    for (int n = 0; n < 8; n++) {
        float v = fv[n];
        float af = fabsf(v);
        acc[0] += v;
        float l[8];
#pragma unroll
        for (int j = 0; j < 8; j++) l[j] = lam_s[j][n0 + n];   // smem broadcast
#pragma unroll
        for (int j = 0; j < 8; j++) acc[1 + j] += l[j] * af;
#pragma unroll
        for (int j1 = 0; j1 < 8; j1++) {
            float t = l[j1] * af;
#pragma unroll
            for (int j2 = 0; j2 < 8; j2++)
                acc[9 + j1 * 8 + j2] += l[j2] * t;
        }
    }

    // Combine halves through smem, half 1 stores this block's partials.
    if (half == 0) {
#pragma unroll
        for (int k = 0; k < NK; k++) comb[k][d] = acc[k];
    }
    __syncthreads();
    if (half == 1) {
        float* p = g_partial + (size_t)b * NOUT + d;
#pragma unroll
        for (int k = 0; k < NK; k++)
            p[k * D_F] = acc[k] + comb[k][d];
    }

    // ---------------- Grid barrier (128 co-resident blocks) ----------------
    __threadfence();                 // publish g_partial before arriving
    __syncthreads();
    if (tid == 0) {
        int old = atomicAdd(&g_ct, 1);
        s_target = (old / NBLK + 1) * NBLK;
    }
    __syncthreads();
    if (tid == 0) {
        while (*(volatile int*)&g_ct < s_target)
            __nanosleep(32);
    }
    __syncthreads();
    __threadfence();                 // acquire: see all blocks' partials

    // ---------------- Phase B: parallel reduce ----------------
    // 2 threads per output; each sums 64 of the 128 block-partials (L2-hot).
    const int gtid = b * 256 + tid;
    if (gtid < 2 * NOUT) {
        const int i = gtid >> 1;
        const int part = gtid & 1;
        const float* p = g_partial + (size_t)part * 64 * NOUT + i;
        float s0 = 0.f, s1 = 0.f, s2 = 0.f, s3 = 0.f;
        float s4 = 0.f, s5 = 0.f, s6 = 0.f, s7 = 0.f;
#pragma unroll
        for (int k = 0; k < 64; k += 8) {
            s0 += p[(k + 0) * NOUT];
            s1 += p[(k + 1) * NOUT];
            s2 += p[(k + 2) * NOUT];
            s3 += p[(k + 3) * NOUT];
            s4 += p[(k + 4) * NOUT];
            s5 += p[(k + 5) * NOUT];
            s6 += p[(k + 6) * NOUT];
            s7 += p[(k + 7) * NOUT];
        }
        float s = (((s0 + s1) + (s2 + s3)) + ((s4 + s5) + (s6 + s7)));
        atomicAdd(out + i, s * (1.0f / (float)V_NODES));
    }
}

// ---------------------------------------------------------------------------
extern "C" void kernel_launch(void* const* d_in, const int* in_sizes, int n_in,
                              void* d_out, int out_size) {
    const float* W = (const float*)d_in[0];
    const float* f = (const float*)d_in[1];
    float* out = (float*)d_out;

    deg_part_kernel<<<2 * CHUNKS, 256>>>(W, out);
    scat_kernel<<<NBLK, 256>>>(f, out);
}